// round 3
// baseline (speedup 1.0000x reference)
#include <cuda_runtime.h>

// Problem constants (fixed by the dataset).
#define C_DIM 128
#define MAXN  100000

// Scratch (allocation-free rule: __device__ globals).
__device__ float g_h0[(size_t)MAXN * C_DIM];   // (1+eps)*x + agg
__device__ float g_h1[(size_t)MAXN * C_DIM];   // relu(h0 @ W1 + b1)

// ---------------------------------------------------------------------------
// Kernel 1: h0 = (1 + eps) * x    (vectorized, one float4 per thread)
// ---------------------------------------------------------------------------
__global__ void init_kernel(const float* __restrict__ x,
                            const float* __restrict__ eps,
                            int n4) {
    int i = blockIdx.x * blockDim.x + threadIdx.x;
    if (i >= n4) return;
    float s = 1.0f + eps[0];
    float4 v = ((const float4*)x)[i];
    v.x *= s; v.y *= s; v.z *= s; v.w *= s;
    ((float4*)g_h0)[i] = v;
}

// ---------------------------------------------------------------------------
// Kernel 2: one warp per edge. Each lane moves 4 floats:
//   load  x[src][lane*4 .. +3]   (LDG.128, L2-resident)
//   red   h0[dst][lane*4 .. +3]  (REDG.128, no return value)
// Indices arrive as int32 (harness converts int64 -> int32).
// ---------------------------------------------------------------------------
__global__ void edge_kernel(const float* __restrict__ x,
                            const int* __restrict__ src,
                            const int* __restrict__ dst,
                            int E, int Nnodes) {
    int e = (int)(((unsigned)blockIdx.x * blockDim.x + threadIdx.x) >> 5);
    if (e >= E) return;
    int lane = threadIdx.x & 31;
    int s = src[e];                 // lane-uniform -> broadcast load
    int d = dst[e];
    // Validity guard: converts a dtype/layout surprise into a rel_err
    // failure instead of an illegal access. Never taken on valid data.
    if ((unsigned)s >= (unsigned)Nnodes || (unsigned)d >= (unsigned)Nnodes)
        return;
    float4 v = __ldg((const float4*)(x + (size_t)s * C_DIM) + lane);
    float* p = g_h0 + (size_t)d * C_DIM + (lane << 2);
    asm volatile("red.global.add.v4.f32 [%0], {%1,%2,%3,%4};"
                 :: "l"(p), "f"(v.x), "f"(v.y), "f"(v.z), "f"(v.w)
                 : "memory");
}

// ---------------------------------------------------------------------------
// Kernels 3/4: Y = relu(A @ W + b)          (FINAL=false, A=g_h0 -> g_h1)
//              Y = relu(relu(A @ W + b) + bias)  (FINAL=true, A=g_h1 -> out)
//
// Tile: 128(M) x 128(N), K staged in chunks of 16.
// Block: 256 threads as 16x16, each thread owns an 8x8 micro-tile.
// A chunk stored transposed in smem (As[k][m]) so both fragments load as
// float4; W chunk stored natural (Ws[k][n]).
// ---------------------------------------------------------------------------
template <bool FINAL>
__global__ void gemm_relu_kernel(const float* __restrict__ A,
                                 const float* __restrict__ W,
                                 const float* __restrict__ b,
                                 const float* __restrict__ bias2,
                                 float* __restrict__ Y,
                                 int M) {
    __shared__ __align__(16) float As[16][132];   // pad: 132 (16B-aligned rows)
    __shared__ __align__(16) float Ws[16][128];

    const int tid = threadIdx.x;
    const int ty  = tid >> 4;     // 0..15  -> row group (8 rows)
    const int tx  = tid & 15;     // 0..15  -> col group (8 cols)
    const int row0 = blockIdx.x * 128;

    float acc[8][8];
    #pragma unroll
    for (int i = 0; i < 8; i++)
        #pragma unroll
        for (int j = 0; j < 8; j++) acc[i][j] = 0.0f;

    for (int k0 = 0; k0 < C_DIM; k0 += 16) {
        // Stage A: 128 rows x 16 k-cols, transposed into As[k][m].
        #pragma unroll
        for (int it = 0; it < 2; it++) {
            int idx = it * 256 + tid;           // 0..511
            int r   = idx >> 2;                 // 0..127
            int q   = idx & 3;                  // quad of 4 k's
            int grow = row0 + r;
            float4 v = make_float4(0.f, 0.f, 0.f, 0.f);
            if (grow < M)
                v = *(const float4*)(A + (size_t)grow * C_DIM + k0 + q * 4);
            As[q * 4 + 0][r] = v.x;
            As[q * 4 + 1][r] = v.y;
            As[q * 4 + 2][r] = v.z;
            As[q * 4 + 3][r] = v.w;
        }
        // Stage W: 16 k-rows x 128 cols (contiguous float4s).
        #pragma unroll
        for (int it = 0; it < 2; it++) {
            int idx = it * 256 + tid;           // 0..511
            int kr  = idx >> 5;                 // 0..15
            int q   = idx & 31;                 // 0..31
            *(float4*)&Ws[kr][q * 4] =
                *(const float4*)(W + (size_t)(k0 + kr) * C_DIM + q * 4);
        }
        __syncthreads();

        #pragma unroll
        for (int k = 0; k < 16; k++) {
            float a[8], w[8];
            *(float4*)&a[0] = *(float4*)&As[k][ty * 8];
            *(float4*)&a[4] = *(float4*)&As[k][ty * 8 + 4];
            *(float4*)&w[0] = *(float4*)&Ws[k][tx * 8];
            *(float4*)&w[4] = *(float4*)&Ws[k][tx * 8 + 4];
            #pragma unroll
            for (int i = 0; i < 8; i++)
                #pragma unroll
                for (int j = 0; j < 8; j++)
                    acc[i][j] += a[i] * w[j];
        }
        __syncthreads();
    }

    // Epilogue.
    const int col = tx * 8;
    float bv[8], b2v[8];
    #pragma unroll
    for (int j = 0; j < 8; j++) bv[j] = b[col + j];
    if (FINAL) {
        #pragma unroll
        for (int j = 0; j < 8; j++) b2v[j] = bias2[col + j];
    }
    #pragma unroll
    for (int i = 0; i < 8; i++) {
        int grow = row0 + ty * 8 + i;
        if (grow < M) {
            float o[8];
            #pragma unroll
            for (int j = 0; j < 8; j++) {
                float v = fmaxf(acc[i][j] + bv[j], 0.0f);
                if (FINAL) v = fmaxf(v + b2v[j], 0.0f);
                o[j] = v;
            }
            float* yp = Y + (size_t)grow * C_DIM + col;
            *(float4*)(yp)     = make_float4(o[0], o[1], o[2], o[3]);
            *(float4*)(yp + 4) = make_float4(o[4], o[5], o[6], o[7]);
        }
    }
}

// ---------------------------------------------------------------------------
// Launch. Graph-capturable: kernel launches only on the capture call.
// Symbol addresses are resolved once on the first (correctness) call and
// cached, so the captured call performs zero CUDA API calls besides launches.
// Inputs (metadata order): x, edge_src, edge_dst, W1, b1, W2, b2, eps, bias
// ---------------------------------------------------------------------------
extern "C" void kernel_launch(void* const* d_in, const int* in_sizes, int n_in,
                              void* d_out, int out_size) {
    const float* x    = (const float*)d_in[0];
    const int*   esrc = (const int*)d_in[1];
    const int*   edst = (const int*)d_in[2];
    const float* W1   = (const float*)d_in[3];
    const float* b1   = (const float*)d_in[4];
    const float* W2   = (const float*)d_in[5];
    const float* b2   = (const float*)d_in[6];
    const float* eps  = (const float*)d_in[7];
    const float* bias = (const float*)d_in[8];
    float*       out  = (float*)d_out;

    const int M  = in_sizes[0] / C_DIM;   // 100000
    const int E  = in_sizes[1];           // 1600000
    const int n4 = in_sizes[0] / 4;

    // Resolve scratch addresses once (first call = correctness run, outside
    // graph capture); reuse the cached pointers on the capture call.
    static float* h0 = nullptr;
    static float* h1 = nullptr;
    if (h0 == nullptr) {
        cudaGetSymbolAddress((void**)&h0, g_h0);
        cudaGetSymbolAddress((void**)&h1, g_h1);
    }

    // h0 = (1+eps)*x
    init_kernel<<<(n4 + 255) / 256, 256>>>(x, eps, n4);

    // h0 += segment_sum(x[src] -> dst)   (one warp per edge, 8 edges/block)
    {
        int blocks = (E + 7) / 8;            // 8 edges (warps) per 256-thread block
        edge_kernel<<<blocks, 256>>>(x, esrc, edst, E, M);
    }

    const int gblocks = (M + 127) / 128;
    // h1 = relu(h0 @ W1 + b1)
    gemm_relu_kernel<false><<<gblocks, 256>>>(h0, W1, b1, nullptr, h1, M);
    // out = relu(relu(h1 @ W2 + b2) + bias)
    gemm_relu_kernel<true><<<gblocks, 256>>>(h1, W2, b2, bias, out, M);
}

// round 4
// speedup vs baseline: 1.2159x; 1.2159x over previous
#include <cuda_runtime.h>
#include <cuda_bf16.h>
#include <cstdint>

// Problem constants (fixed by the dataset).
#define C_DIM 128
#define MAXN  100000

// Scratch (allocation-free rule: __device__ globals).
__device__ float g_h0[(size_t)MAXN * C_DIM];   // (1+eps)*x + agg
__device__ float g_h1[(size_t)MAXN * C_DIM];   // relu(h0 @ W1 + b1)

// Pre-packed weights: k-pairs packed into u32 (even k in low half), hi/lo bf16
// split planes. Layout: [mat][kpair (64)][n (128)].
__device__ uint32_t g_Wp_hi[2 * 64 * 128];
__device__ uint32_t g_Wp_lo[2 * 64 * 128];

// ---------------------------------------------------------------------------
// Kernel 0: split W1/W2 into bf16 hi/lo, packed as k-pairs.
//   Wp[mat][kp][n] = pack(bf16(W[2kp][n]), bf16(W[2kp+1][n])), lo = residual.
// ---------------------------------------------------------------------------
__global__ void prepack_w_kernel(const float* __restrict__ W1,
                                 const float* __restrict__ W2) {
    int idx = blockIdx.x * blockDim.x + threadIdx.x;   // 0..16383
    if (idx >= 2 * 64 * 128) return;
    int mat = idx >> 13;
    int r   = idx & 8191;
    int kp  = r >> 7;
    int n   = r & 127;
    const float* W = mat ? W2 : W1;
    float v0 = W[(2 * kp) * C_DIM + n];
    float v1 = W[(2 * kp + 1) * C_DIM + n];
    __nv_bfloat162 hp = __floats2bfloat162_rn(v0, v1);
    __nv_bfloat162 lp = __floats2bfloat162_rn(v0 - __low2float(hp),
                                              v1 - __high2float(hp));
    g_Wp_hi[idx] = *reinterpret_cast<uint32_t*>(&hp);
    g_Wp_lo[idx] = *reinterpret_cast<uint32_t*>(&lp);
}

// ---------------------------------------------------------------------------
// Kernel 1: h0 = (1 + eps) * x
// ---------------------------------------------------------------------------
__global__ void init_kernel(const float* __restrict__ x,
                            const float* __restrict__ eps,
                            int n4) {
    int i = blockIdx.x * blockDim.x + threadIdx.x;
    if (i >= n4) return;
    float s = 1.0f + eps[0];
    float4 v = ((const float4*)x)[i];
    v.x *= s; v.y *= s; v.z *= s; v.w *= s;
    ((float4*)g_h0)[i] = v;
}

// ---------------------------------------------------------------------------
// Kernel 2: one warp per edge; gather LDG.128 + scatter REDG.128.
// ---------------------------------------------------------------------------
__global__ void edge_kernel(const float* __restrict__ x,
                            const int* __restrict__ src,
                            const int* __restrict__ dst,
                            int E, int Nnodes) {
    int e = (int)(((unsigned)blockIdx.x * blockDim.x + threadIdx.x) >> 5);
    if (e >= E) return;
    int lane = threadIdx.x & 31;
    int s = src[e];
    int d = dst[e];
    if ((unsigned)s >= (unsigned)Nnodes || (unsigned)d >= (unsigned)Nnodes)
        return;
    float4 v = __ldg((const float4*)(x + (size_t)s * C_DIM) + lane);
    float* p = g_h0 + (size_t)d * C_DIM + (lane << 2);
    asm volatile("red.global.add.v4.f32 [%0], {%1,%2,%3,%4};"
                 :: "l"(p), "f"(v.x), "f"(v.y), "f"(v.z), "f"(v.w)
                 : "memory");
}

// ---------------------------------------------------------------------------
// Kernels 3/4: bf16x3 tensor-core GEMM + fused epilogue.
//   Y = relu(A @ W + b)                      (FINAL=false)
//   Y = relu(relu(A @ W + b) + bias2)        (FINAL=true)
//
// A is split per-tile into bf16 hi/lo; W comes pre-split. Each output is
// computed as ahi*bhi + ahi*blo + alo*bhi with fp32 accumulation
// (mma.m16n8k16.f32.bf16), giving ~1e-6 relative error.
//
// Block: 256 threads (8 warps as 2m x 4n), tile 64(M) x 128(N), K chunk 32.
// SMEM strides: A rows 20 u32 (bank = 4g+t, bijective -> conflict-free),
// W rows 136 u32 (bank = 8t+g, bijective -> conflict-free).
// ---------------------------------------------------------------------------
#define AS_STRIDE 20
#define WS_STRIDE 136

__device__ __forceinline__ void mma_bf16(float* d, const uint32_t* a,
                                         const uint32_t* b) {
    asm volatile(
        "mma.sync.aligned.m16n8k16.row.col.f32.bf16.bf16.f32 "
        "{%0,%1,%2,%3}, {%4,%5,%6,%7}, {%8,%9}, {%0,%1,%2,%3};"
        : "+f"(d[0]), "+f"(d[1]), "+f"(d[2]), "+f"(d[3])
        : "r"(a[0]), "r"(a[1]), "r"(a[2]), "r"(a[3]), "r"(b[0]), "r"(b[1]));
}

template <bool FINAL>
__global__ void gemm_bf16x3_kernel(const float* __restrict__ A,
                                   const uint32_t* __restrict__ Wp_hi,
                                   const uint32_t* __restrict__ Wp_lo,
                                   const float* __restrict__ b,
                                   const float* __restrict__ bias2,
                                   float* __restrict__ Y,
                                   int M) {
    __shared__ __align__(16) uint32_t As_hi[64 * AS_STRIDE];
    __shared__ __align__(16) uint32_t As_lo[64 * AS_STRIDE];
    __shared__ __align__(16) uint32_t Ws_hi[16 * WS_STRIDE];
    __shared__ __align__(16) uint32_t Ws_lo[16 * WS_STRIDE];

    const int tid  = threadIdx.x;
    const int wid  = tid >> 5;
    const int lane = tid & 31;
    const int g    = lane >> 2;       // group row
    const int t    = lane & 3;        // thread-in-group
    const int warp_m = (wid & 1) * 32;        // 2 warps along M
    const int warp_n = (wid >> 1) * 32;       // 4 warps along N
    const int row0 = blockIdx.x * 64;

    float acc[2][4][4];               // [mtile][ntile][frag]
    #pragma unroll
    for (int i = 0; i < 2; i++)
        #pragma unroll
        for (int j = 0; j < 4; j++)
            #pragma unroll
            for (int r = 0; r < 4; r++) acc[i][j][r] = 0.0f;

    for (int kc = 0; kc < 4; kc++) {
        const int k0  = kc * 32;      // in floats
        const int kp0 = kc * 16;      // in k-pairs

        // ---- Stage A chunk: 64 rows x 32 k, split hi/lo, pack k-pairs ----
        #pragma unroll
        for (int it = 0; it < 2; it++) {
            int idx  = it * 256 + tid;    // 0..511 float4 slots (8 per row)
            int row  = idx >> 3;
            int kq   = idx & 7;
            int grow = row0 + row;
            float4 v = make_float4(0.f, 0.f, 0.f, 0.f);
            if (grow < M)
                v = *(const float4*)(A + (size_t)grow * C_DIM + k0 + kq * 4);
            __nv_bfloat162 hp0 = __floats2bfloat162_rn(v.x, v.y);
            __nv_bfloat162 lp0 = __floats2bfloat162_rn(v.x - __low2float(hp0),
                                                       v.y - __high2float(hp0));
            __nv_bfloat162 hp1 = __floats2bfloat162_rn(v.z, v.w);
            __nv_bfloat162 lp1 = __floats2bfloat162_rn(v.z - __low2float(hp1),
                                                       v.w - __high2float(hp1));
            int o = row * AS_STRIDE + kq * 2;
            As_hi[o]     = *reinterpret_cast<uint32_t*>(&hp0);
            As_hi[o + 1] = *reinterpret_cast<uint32_t*>(&hp1);
            As_lo[o]     = *reinterpret_cast<uint32_t*>(&lp0);
            As_lo[o + 1] = *reinterpret_cast<uint32_t*>(&lp1);
        }
        // ---- Stage W chunk: 16 kpair-rows x 128 n, both planes ----
        #pragma unroll
        for (int it = 0; it < 2; it++) {
            int idx  = it * 256 + tid;    // 0..511 uint4 slots (32 per row)
            int krow = idx >> 5;
            int c4   = idx & 31;
            uint4 vh = *(const uint4*)(Wp_hi + (size_t)(kp0 + krow) * 128 + c4 * 4);
            uint4 vl = *(const uint4*)(Wp_lo + (size_t)(kp0 + krow) * 128 + c4 * 4);
            *(uint4*)&Ws_hi[krow * WS_STRIDE + c4 * 4] = vh;
            *(uint4*)&Ws_lo[krow * WS_STRIDE + c4 * 4] = vl;
        }
        __syncthreads();

        // ---- Compute: 2 k16 steps per chunk ----
        #pragma unroll
        for (int ks = 0; ks < 2; ks++) {
            uint32_t a_hi[2][4], a_lo[2][4], b_hi[4][2], b_lo[4][2];
            #pragma unroll
            for (int mt = 0; mt < 2; mt++) {
                int base = (warp_m + mt * 16 + g) * AS_STRIDE + ks * 8 + t;
                a_hi[mt][0] = As_hi[base];
                a_hi[mt][1] = As_hi[base + 8 * AS_STRIDE];
                a_hi[mt][2] = As_hi[base + 4];
                a_hi[mt][3] = As_hi[base + 8 * AS_STRIDE + 4];
                a_lo[mt][0] = As_lo[base];
                a_lo[mt][1] = As_lo[base + 8 * AS_STRIDE];
                a_lo[mt][2] = As_lo[base + 4];
                a_lo[mt][3] = As_lo[base + 8 * AS_STRIDE + 4];
            }
            #pragma unroll
            for (int nt = 0; nt < 4; nt++) {
                int bcol = warp_n + nt * 8 + g;
                int br   = (ks * 8 + t) * WS_STRIDE + bcol;
                b_hi[nt][0] = Ws_hi[br];
                b_hi[nt][1] = Ws_hi[br + 4 * WS_STRIDE];
                b_lo[nt][0] = Ws_lo[br];
                b_lo[nt][1] = Ws_lo[br + 4 * WS_STRIDE];
            }
            #pragma unroll
            for (int mt = 0; mt < 2; mt++)
                #pragma unroll
                for (int nt = 0; nt < 4; nt++) {
                    mma_bf16(acc[mt][nt], a_hi[mt], b_hi[nt]);
                    mma_bf16(acc[mt][nt], a_hi[mt], b_lo[nt]);
                    mma_bf16(acc[mt][nt], a_lo[mt], b_hi[nt]);
                }
        }
        __syncthreads();
    }

    // ---- Epilogue: bias + relu (+bias2 + relu), fp32 stores ----
    #pragma unroll
    for (int nt = 0; nt < 4; nt++) {
        int c0 = warp_n + nt * 8 + 2 * t;
        float2 bb = *(const float2*)(b + c0);
        float2 b2 = make_float2(0.f, 0.f);
        if (FINAL) b2 = *(const float2*)(bias2 + c0);
        #pragma unroll
        for (int mt = 0; mt < 2; mt++) {
            int r0 = row0 + warp_m + mt * 16 + g;
            float v0 = fmaxf(acc[mt][nt][0] + bb.x, 0.0f);
            float v1 = fmaxf(acc[mt][nt][1] + bb.y, 0.0f);
            float v2 = fmaxf(acc[mt][nt][2] + bb.x, 0.0f);
            float v3 = fmaxf(acc[mt][nt][3] + bb.y, 0.0f);
            if (FINAL) {
                v0 = fmaxf(v0 + b2.x, 0.0f);
                v1 = fmaxf(v1 + b2.y, 0.0f);
                v2 = fmaxf(v2 + b2.x, 0.0f);
                v3 = fmaxf(v3 + b2.y, 0.0f);
            }
            if (r0 < M)
                *(float2*)(Y + (size_t)r0 * C_DIM + c0) = make_float2(v0, v1);
            if (r0 + 8 < M)
                *(float2*)(Y + (size_t)(r0 + 8) * C_DIM + c0) = make_float2(v2, v3);
        }
    }
}

// ---------------------------------------------------------------------------
// Launch. Graph-capturable: kernel launches only on the capture call.
// Inputs (metadata order): x, edge_src, edge_dst, W1, b1, W2, b2, eps, bias
// ---------------------------------------------------------------------------
extern "C" void kernel_launch(void* const* d_in, const int* in_sizes, int n_in,
                              void* d_out, int out_size) {
    const float* x    = (const float*)d_in[0];
    const int*   esrc = (const int*)d_in[1];
    const int*   edst = (const int*)d_in[2];
    const float* W1   = (const float*)d_in[3];
    const float* b1   = (const float*)d_in[4];
    const float* W2   = (const float*)d_in[5];
    const float* b2   = (const float*)d_in[6];
    const float* eps  = (const float*)d_in[7];
    const float* bias = (const float*)d_in[8];
    float*       out  = (float*)d_out;

    const int M  = in_sizes[0] / C_DIM;   // 100000
    const int E  = in_sizes[1];           // 1600000
    const int n4 = in_sizes[0] / 4;

    // Resolve scratch addresses once (first call = correctness run, outside
    // graph capture); reuse cached pointers on the capture call.
    static float*    h0 = nullptr;
    static float*    h1 = nullptr;
    static uint32_t* wph = nullptr;
    static uint32_t* wpl = nullptr;
    if (h0 == nullptr) {
        cudaGetSymbolAddress((void**)&h0,  g_h0);
        cudaGetSymbolAddress((void**)&h1,  g_h1);
        cudaGetSymbolAddress((void**)&wph, g_Wp_hi);
        cudaGetSymbolAddress((void**)&wpl, g_Wp_lo);
    }

    // W split/pack (recomputed every call; ~3us).
    prepack_w_kernel<<<64, 256>>>(W1, W2);

    // h0 = (1+eps)*x
    init_kernel<<<(n4 + 255) / 256, 256>>>(x, eps, n4);

    // h0 += segment_sum(x[src] -> dst)
    edge_kernel<<<(E + 7) / 8, 256>>>(x, esrc, edst, E, M);

    const int gblocks = (M + 63) / 64;
    // h1 = relu(h0 @ W1 + b1)
    gemm_bf16x3_kernel<false><<<gblocks, 256>>>(h0, wph, wpl, b1, nullptr, h1, M);
    // out = relu(relu(h1 @ W2 + b2) + bias)
    gemm_bf16x3_kernel<true><<<gblocks, 256>>>(h1, wph + 64 * 128, wpl + 64 * 128,
                                               b2, bias, out, M);
}

// round 5
// speedup vs baseline: 2.1849x; 1.7970x over previous
#include <cuda_runtime.h>
#include <cuda_bf16.h>
#include <cstdint>

// Problem constants (fixed by the dataset).
#define C_DIM 128
#define MAXN  100000
#define MAXE  1700000
#define NPAD  (MAXN + 64)          // slack rows stay zero (zero-init .bss)

// ---------------------------------------------------------------------------
// Scratch (__device__ globals; allocation-free rule).
// Feature planes: bf16 hi/lo split, k-pairs packed into u32 (even k = low
// half). Layout: [row][64 u32].
// ---------------------------------------------------------------------------
__device__ uint32_t g_h0_hi[(size_t)NPAD * 64];
__device__ uint32_t g_h0_lo[(size_t)NPAD * 64];
__device__ uint32_t g_h1_hi[(size_t)NPAD * 64];
__device__ uint32_t g_h1_lo[(size_t)NPAD * 64];
__device__ uint32_t g_Wp_hi[2 * 64 * 128];   // [mat][kpair][n]
__device__ uint32_t g_Wp_lo[2 * 64 * 128];
// CSR build state.
__device__ int g_deg[MAXN];
__device__ int g_offs[MAXN];
__device__ int g_cur[MAXN];
__device__ int g_part[256];
__device__ int g_csr[MAXE];

// ---------------------------------------------------------------------------
// W prepack: split into bf16 hi/lo, packed as k-pairs.
// ---------------------------------------------------------------------------
__global__ void prepack_w_kernel(const float* __restrict__ W1,
                                 const float* __restrict__ W2) {
    int idx = blockIdx.x * blockDim.x + threadIdx.x;   // 0..16383
    if (idx >= 2 * 64 * 128) return;
    int mat = idx >> 13, r = idx & 8191, kp = r >> 7, n = r & 127;
    const float* W = mat ? W2 : W1;
    float v0 = W[(2 * kp) * C_DIM + n];
    float v1 = W[(2 * kp + 1) * C_DIM + n];
    __nv_bfloat162 hp = __floats2bfloat162_rn(v0, v1);
    __nv_bfloat162 lp = __floats2bfloat162_rn(v0 - __low2float(hp),
                                              v1 - __high2float(hp));
    g_Wp_hi[idx] = *reinterpret_cast<uint32_t*>(&hp);
    g_Wp_lo[idx] = *reinterpret_cast<uint32_t*>(&lp);
}

// ---------------------------------------------------------------------------
// CSR build: zero -> histogram -> exclusive scan (3 kernels) -> scatter.
// ---------------------------------------------------------------------------
__global__ void zero_deg_kernel(int Nn) {
    int i = blockIdx.x * blockDim.x + threadIdx.x;
    if (i < Nn) g_deg[i] = 0;
}

__global__ void hist_kernel(const int* __restrict__ src,
                            const int* __restrict__ dst, int E, int Nn) {
    int e = blockIdx.x * blockDim.x + threadIdx.x;
    if (e >= E) return;
    int s = src[e], d = dst[e];
    if ((unsigned)s >= (unsigned)Nn || (unsigned)d >= (unsigned)Nn) return;
    atomicAdd(&g_deg[d], 1);
}

__global__ void scan1_kernel(int Nn) {            // 512 threads/block
    __shared__ int sh[512];
    int tid = threadIdx.x;
    int gid = blockIdx.x * 512 + tid;
    int v = (gid < Nn) ? g_deg[gid] : 0;
    sh[tid] = v;
    __syncthreads();
    #pragma unroll
    for (int ofs = 1; ofs < 512; ofs <<= 1) {
        int t = (tid >= ofs) ? sh[tid - ofs] : 0;
        __syncthreads();
        sh[tid] += t;
        __syncthreads();
    }
    if (gid < Nn) g_offs[gid] = sh[tid] - v;      // exclusive within block
    if (tid == 511) g_part[blockIdx.x] = sh[511];
}

__global__ void scan2_kernel(int nb) {            // <<<1,1>>>
    int run = 0;
    for (int b = 0; b < nb; b++) { int t = g_part[b]; g_part[b] = run; run += t; }
}

__global__ void scan3_kernel(int Nn) {            // 512 threads/block
    int gid = blockIdx.x * 512 + threadIdx.x;
    if (gid >= Nn) return;
    int o = g_offs[gid] + g_part[blockIdx.x];
    g_offs[gid] = o;
    g_cur[gid]  = o;
}

__global__ void scatter_kernel(const int* __restrict__ src,
                               const int* __restrict__ dst, int E, int Nn) {
    int e = blockIdx.x * blockDim.x + threadIdx.x;
    if (e >= E) return;
    int s = src[e], d = dst[e];
    if ((unsigned)s >= (unsigned)Nn || (unsigned)d >= (unsigned)Nn) return;
    int pos = atomicAdd(&g_cur[d], 1);
    g_csr[pos] = s;
}

// ---------------------------------------------------------------------------
// Gather: one warp per dst node. Sums x[src] rows (plain LDG.128, no
// atomics), adds (1+eps)*x[dst], writes h0 as split bf16 hi/lo planes.
// ---------------------------------------------------------------------------
__global__ void gather_kernel(const float* __restrict__ x,
                              const float* __restrict__ eps, int Nn) {
    int w = (int)(((unsigned)blockIdx.x * blockDim.x + threadIdx.x) >> 5);
    if (w >= Nn) return;
    int lane = threadIdx.x & 31;
    int off = g_offs[w];
    int d   = g_deg[w];

    float ax = 0.f, ay = 0.f, az = 0.f, aw = 0.f;
    int i = 0;
    for (; i + 1 < d; i += 2) {                  // 2-way unroll for MLP
        int s0 = g_csr[off + i];
        int s1 = g_csr[off + i + 1];
        float4 v0 = __ldg((const float4*)(x + (size_t)s0 * C_DIM) + lane);
        float4 v1 = __ldg((const float4*)(x + (size_t)s1 * C_DIM) + lane);
        ax += v0.x + v1.x; ay += v0.y + v1.y;
        az += v0.z + v1.z; aw += v0.w + v1.w;
    }
    if (i < d) {
        int s0 = g_csr[off + i];
        float4 v0 = __ldg((const float4*)(x + (size_t)s0 * C_DIM) + lane);
        ax += v0.x; ay += v0.y; az += v0.z; aw += v0.w;
    }
    float sc = 1.0f + eps[0];
    float4 xv = __ldg((const float4*)(x + (size_t)w * C_DIM) + lane);
    ax = fmaf(sc, xv.x, ax); ay = fmaf(sc, xv.y, ay);
    az = fmaf(sc, xv.z, az); aw = fmaf(sc, xv.w, aw);

    __nv_bfloat162 hp0 = __floats2bfloat162_rn(ax, ay);
    __nv_bfloat162 lp0 = __floats2bfloat162_rn(ax - __low2float(hp0),
                                               ay - __high2float(hp0));
    __nv_bfloat162 hp1 = __floats2bfloat162_rn(az, aw);
    __nv_bfloat162 lp1 = __floats2bfloat162_rn(az - __low2float(hp1),
                                               aw - __high2float(hp1));
    size_t o = (size_t)w * 64 + 2 * lane;
    *(uint2*)(g_h0_hi + o) = make_uint2(*reinterpret_cast<uint32_t*>(&hp0),
                                        *reinterpret_cast<uint32_t*>(&hp1));
    *(uint2*)(g_h0_lo + o) = make_uint2(*reinterpret_cast<uint32_t*>(&lp0),
                                        *reinterpret_cast<uint32_t*>(&lp1));
}

// ---------------------------------------------------------------------------
// bf16x3 tensor-core GEMM, cp.async double-buffered, pre-split operands.
//   FINAL=false: Yplanes = split(relu(A @ W + b))
//   FINAL=true : Yf = relu(relu(A @ W + b) + bias2)
// Block: 256 threads (8 warps as 2m x 4n), tile 64(M) x 128(N), K chunk 32.
// SMEM (dynamic, 2 stages): A planes stride 20 u32, W planes stride 136 u32
// (both bank-conflict-free for the fragment pattern, 16B-aligned for cp.async).
// ---------------------------------------------------------------------------
#define AS_STRIDE 20
#define WS_STRIDE 136
#define STAGE_U32 6912         // 2*64*20 + 2*16*136
#define GEMM_SMEM_BYTES (2 * STAGE_U32 * 4)

__device__ __forceinline__ void cp16(uint32_t s_dst, const void* g_src) {
    asm volatile("cp.async.cg.shared.global [%0], [%1], 16;"
                 :: "r"(s_dst), "l"(g_src) : "memory");
}
__device__ __forceinline__ void cp_commit() {
    asm volatile("cp.async.commit_group;" ::: "memory");
}
template <int N>
__device__ __forceinline__ void cp_wait() {
    asm volatile("cp.async.wait_group %0;" :: "n"(N) : "memory");
}

__device__ __forceinline__ void mma_bf16(float* d, const uint32_t* a,
                                         const uint32_t* b) {
    asm volatile(
        "mma.sync.aligned.m16n8k16.row.col.f32.bf16.bf16.f32 "
        "{%0,%1,%2,%3}, {%4,%5,%6,%7}, {%8,%9}, {%0,%1,%2,%3};"
        : "+f"(d[0]), "+f"(d[1]), "+f"(d[2]), "+f"(d[3])
        : "r"(a[0]), "r"(a[1]), "r"(a[2]), "r"(a[3]), "r"(b[0]), "r"(b[1]));
}

template <bool FINAL>
__global__ void gemm_tc_kernel(const uint32_t* __restrict__ Ah,
                               const uint32_t* __restrict__ Al,
                               const uint32_t* __restrict__ Wh,
                               const uint32_t* __restrict__ Wl,
                               const float* __restrict__ b,
                               const float* __restrict__ bias2,
                               uint32_t* __restrict__ Yh,
                               uint32_t* __restrict__ Yl,
                               float* __restrict__ Yf,
                               int M) {
    extern __shared__ uint32_t smem[];

    const int tid  = threadIdx.x;
    const int wid  = tid >> 5;
    const int lane = tid & 31;
    const int g    = lane >> 2;
    const int t    = lane & 3;
    const int warp_m = (wid & 1) * 32;
    const int warp_n = (wid >> 1) * 32;
    const int row0 = blockIdx.x * 64;

    // Staging indices (constant per thread).
    const int a_row = tid >> 2, a_q = tid & 3;

    auto issue = [&](int kc, int st) {
        uint32_t* base = smem + st * STAGE_U32;
        uint32_t sb = (uint32_t)__cvta_generic_to_shared(base);
        // A planes: 1 x 16B per plane per thread.
        size_t asrc = (size_t)(row0 + a_row) * 64 + kc * 16 + a_q * 4;
        uint32_t adst = sb + (a_row * AS_STRIDE + a_q * 4) * 4;
        cp16(adst, Ah + asrc);
        cp16(adst + 1280 * 4, Al + asrc);
        // W planes: 2 x 16B per plane per thread.
        #pragma unroll
        for (int it = 0; it < 2; it++) {
            int idx = it * 256 + tid;
            int krow = idx >> 5, c4 = idx & 31;
            size_t wsrc = (size_t)(kc * 16 + krow) * 128 + c4 * 4;
            uint32_t wdst = sb + (2560 + krow * WS_STRIDE + c4 * 4) * 4;
            cp16(wdst, Wh + wsrc);
            cp16(wdst + 2176 * 4, Wl + wsrc);
        }
    };

    float acc[2][4][4];
    #pragma unroll
    for (int i = 0; i < 2; i++)
        #pragma unroll
        for (int j = 0; j < 4; j++)
            #pragma unroll
            for (int r = 0; r < 4; r++) acc[i][j][r] = 0.0f;

    issue(0, 0);
    cp_commit();

    for (int kc = 0; kc < 4; kc++) {
        if (kc < 3) { issue(kc + 1, (kc + 1) & 1); cp_commit(); cp_wait<1>(); }
        else        { cp_wait<0>(); }
        __syncthreads();

        const uint32_t* base = smem + (kc & 1) * STAGE_U32;
        const uint32_t* As_hi = base;
        const uint32_t* As_lo = base + 1280;
        const uint32_t* Ws_hi = base + 2560;
        const uint32_t* Ws_lo = base + 4736;

        #pragma unroll
        for (int ks = 0; ks < 2; ks++) {
            uint32_t a_hi[2][4], a_lo[2][4], b_hi[4][2], b_lo[4][2];
            #pragma unroll
            for (int mt = 0; mt < 2; mt++) {
                int bi = (warp_m + mt * 16 + g) * AS_STRIDE + ks * 8 + t;
                a_hi[mt][0] = As_hi[bi];
                a_hi[mt][1] = As_hi[bi + 8 * AS_STRIDE];
                a_hi[mt][2] = As_hi[bi + 4];
                a_hi[mt][3] = As_hi[bi + 8 * AS_STRIDE + 4];
                a_lo[mt][0] = As_lo[bi];
                a_lo[mt][1] = As_lo[bi + 8 * AS_STRIDE];
                a_lo[mt][2] = As_lo[bi + 4];
                a_lo[mt][3] = As_lo[bi + 8 * AS_STRIDE + 4];
            }
            #pragma unroll
            for (int nt = 0; nt < 4; nt++) {
                int br = (ks * 8 + t) * WS_STRIDE + warp_n + nt * 8 + g;
                b_hi[nt][0] = Ws_hi[br];
                b_hi[nt][1] = Ws_hi[br + 4 * WS_STRIDE];
                b_lo[nt][0] = Ws_lo[br];
                b_lo[nt][1] = Ws_lo[br + 4 * WS_STRIDE];
            }
            #pragma unroll
            for (int mt = 0; mt < 2; mt++)
                #pragma unroll
                for (int nt = 0; nt < 4; nt++) {
                    mma_bf16(acc[mt][nt], a_hi[mt], b_hi[nt]);
                    mma_bf16(acc[mt][nt], a_hi[mt], b_lo[nt]);
                    mma_bf16(acc[mt][nt], a_lo[mt], b_hi[nt]);
                }
        }
        __syncthreads();
    }

    // Epilogue.
    #pragma unroll
    for (int nt = 0; nt < 4; nt++) {
        int c0 = warp_n + nt * 8 + 2 * t;
        float2 bb = *(const float2*)(b + c0);
        float2 b2 = make_float2(0.f, 0.f);
        if (FINAL) b2 = *(const float2*)(bias2 + c0);
        #pragma unroll
        for (int mt = 0; mt < 2; mt++) {
            #pragma unroll
            for (int h = 0; h < 2; h++) {
                int r = row0 + warp_m + mt * 16 + g + h * 8;
                if (r >= M) continue;
                float v0 = fmaxf(acc[mt][nt][h * 2 + 0] + bb.x, 0.0f);
                float v1 = fmaxf(acc[mt][nt][h * 2 + 1] + bb.y, 0.0f);
                if (FINAL) {
                    v0 = fmaxf(v0 + b2.x, 0.0f);
                    v1 = fmaxf(v1 + b2.y, 0.0f);
                    *(float2*)(Yf + (size_t)r * C_DIM + c0) = make_float2(v0, v1);
                } else {
                    __nv_bfloat162 hp = __floats2bfloat162_rn(v0, v1);
                    __nv_bfloat162 lp = __floats2bfloat162_rn(
                        v0 - __low2float(hp), v1 - __high2float(hp));
                    size_t o = (size_t)r * 64 + (c0 >> 1);
                    Yh[o] = *reinterpret_cast<uint32_t*>(&hp);
                    Yl[o] = *reinterpret_cast<uint32_t*>(&lp);
                }
            }
        }
    }
}

// ---------------------------------------------------------------------------
// Launch. Capture call performs only kernel launches; symbol addresses and
// func attributes resolved once on the first (correctness) call.
// Inputs (metadata order): x, edge_src, edge_dst, W1, b1, W2, b2, eps, bias
// ---------------------------------------------------------------------------
extern "C" void kernel_launch(void* const* d_in, const int* in_sizes, int n_in,
                              void* d_out, int out_size) {
    const float* x    = (const float*)d_in[0];
    const int*   esrc = (const int*)d_in[1];
    const int*   edst = (const int*)d_in[2];
    const float* W1   = (const float*)d_in[3];
    const float* b1   = (const float*)d_in[4];
    const float* W2   = (const float*)d_in[5];
    const float* b2   = (const float*)d_in[6];
    const float* eps  = (const float*)d_in[7];
    const float* bias = (const float*)d_in[8];
    float*       out  = (float*)d_out;

    const int M = in_sizes[0] / C_DIM;    // 100000
    const int E = in_sizes[1];            // 1600000

    static uint32_t *h0h = nullptr, *h0l, *h1h, *h1l, *wph, *wpl;
    if (h0h == nullptr) {
        cudaGetSymbolAddress((void**)&h0h, g_h0_hi);
        cudaGetSymbolAddress((void**)&h0l, g_h0_lo);
        cudaGetSymbolAddress((void**)&h1h, g_h1_hi);
        cudaGetSymbolAddress((void**)&h1l, g_h1_lo);
        cudaGetSymbolAddress((void**)&wph, g_Wp_hi);
        cudaGetSymbolAddress((void**)&wpl, g_Wp_lo);
        cudaFuncSetAttribute(gemm_tc_kernel<false>,
                             cudaFuncAttributeMaxDynamicSharedMemorySize,
                             GEMM_SMEM_BYTES);
        cudaFuncSetAttribute(gemm_tc_kernel<true>,
                             cudaFuncAttributeMaxDynamicSharedMemorySize,
                             GEMM_SMEM_BYTES);
    }

    const int nb = (M + 511) / 512;       // scan blocks

    prepack_w_kernel<<<64, 256>>>(W1, W2);

    // CSR build.
    zero_deg_kernel<<<(M + 255) / 256, 256>>>(M);
    hist_kernel<<<(E + 255) / 256, 256>>>(esrc, edst, E, M);
    scan1_kernel<<<nb, 512>>>(M);
    scan2_kernel<<<1, 1>>>(nb);
    scan3_kernel<<<nb, 512>>>(M);
    scatter_kernel<<<(E + 255) / 256, 256>>>(esrc, edst, E, M);

    // h0 = (1+eps)*x + gather-sum, written as split planes.
    gather_kernel<<<(M + 7) / 8, 256>>>(x, eps, M);

    const int gblocks = (M + 63) / 64;
    // h1 = relu(h0 @ W1 + b1)  (split planes out)
    gemm_tc_kernel<false><<<gblocks, 256, GEMM_SMEM_BYTES>>>(
        h0h, h0l, wph, wpl, b1, nullptr, h1h, h1l, nullptr, M);
    // out = relu(relu(h1 @ W2 + b2) + bias)
    gemm_tc_kernel<true><<<gblocks, 256, GEMM_SMEM_BYTES>>>(
        h1h, h1l, wph + 64 * 128, wpl + 64 * 128, b2, bias,
        nullptr, nullptr, out, M);
}